// round 11
// baseline (speedup 1.0000x reference)
#include <cuda_runtime.h>
#include <cuda_bf16.h>

// Per-channel class frequencies (compile-time constants from the reference).
__constant__ float c_W[23] = {
    0.0012597430655963838f, 0.0004919313290455535f, 0.0021106513104319356f,
    0.0007678117365508301f, 0.004719881670572202f,  0.000372272357115554f,
    0.029090425620315438f,  0.010056339432617042f,  0.0034817436971298467f,
    0.0003057951504877765f, 0.003995280118329428f,  8.808229878180519e-05f,
    0.012070598793438699f,  0.016788818533845208f,  0.0017832510677901316f,
    0.0008758371973209686f, 0.0005933090691529143f, 0.0031992155689617922f,
    0.003212511010287348f,  0.0016685778863572154f, 0.0009356666832859684f,
    0.0010985358395240233f, 0.00103372056306194f
};

// 1184 = 8 CTAs x 148 SMs: balanced single wave (best-known grid).
#define NBLOCKS 1184
#define NTHREADS 256
#define LN2F 0.6931471805599453f

// Scratch (no allocations allowed). Every g_part slot is written every run;
// g_count self-wraps to 0 via atomicInc -> graph-replay safe.
__device__ float    g_part[NBLOCKS];
__device__ unsigned g_count = 0;

// Blackwell 256-bit global load (halves LDG issue count vs 128-bit).
// Plain .nc, no evict hints (R7 showed evict_last poisons L2).
__device__ __forceinline__ void ld256(const void* p, uint4& a, uint4& b) {
    asm("ld.global.nc.v8.b32 {%0,%1,%2,%3,%4,%5,%6,%7}, [%8];"
        : "=r"(a.x), "=r"(a.y), "=r"(a.z), "=r"(a.w),
          "=r"(b.x), "=r"(b.y), "=r"(b.z), "=r"(b.w)
        : "l"(p));
}

__global__ __launch_bounds__(NTHREADS, 8)
void bce_fused_kernel(const float* __restrict__ x,
                      const int*   __restrict__ l,
                      int n_u8, int rem, int tail_base,
                      float* __restrict__ out, float inv_n) {
    __shared__ float  s_w0[23];   // ln2*(W+1)   : weight when label==0
    __shared__ float  s_w1[23];   // ln2*(1+1/W) : weight when label==1
    __shared__ float  s_part[NTHREADS / 32];
    __shared__ double s_dpart[NTHREADS / 32];
    __shared__ bool   s_is_last;

    const int t = threadIdx.x;
    if (t < 23) {
        float w = c_W[t];
        s_w0[t] = LN2F * (w + 1.0f);
        s_w1[t] = LN2F * (1.0f + __frcp_rn(w));
    }
    __syncthreads();

    const int stride = NBLOCKS * NTHREADS;
    const int gtid   = blockIdx.x * NTHREADS + t;

    // Channel of the first element of this thread's first 8-group, and the
    // per-iteration advance (8*stride mod 23).
    int c_base = (int)((8ll * (long long)gtid) % 23);
    const int d = (int)((8ll * (long long)stride) % 23);

    float acc = 0.0f;

    // Grid-stride loop over 8-element units: 2 LDG.256 per iteration.
    for (int v = gtid; v < n_u8; v += stride) {
        uint4 xa, xb, la, lb;
        ld256(x + 8ll * v, xa, xb);
        ld256(l + 8ll * v, la, lb);

        int c = c_base;
        c_base += d; if (c_base >= 23) c_base -= 23;

        float xs[8] = { __uint_as_float(xa.x), __uint_as_float(xa.y),
                        __uint_as_float(xa.z), __uint_as_float(xa.w),
                        __uint_as_float(xb.x), __uint_as_float(xb.y),
                        __uint_as_float(xb.z), __uint_as_float(xb.w) };
        int   ls[8] = { (int)la.x, (int)la.y, (int)la.z, (int)la.w,
                        (int)lb.x, (int)lb.y, (int)lb.z, (int)lb.w };
        #pragma unroll
        for (int j = 0; j < 8; ++j) {
            bool  pos = (ls[j] > 0);
            float arg = pos ? xs[j] : (1.0f - xs[j]);
            const float* tab = pos ? s_w1 : s_w0;   // one LDS per element
            acc = fmaf(tab[c], -__log2f(arg), acc);
            c = (c == 22) ? 0 : (c + 1);
        }
    }

    // Scalar tail (n % 8 elements; 0 for B*C = 23e6 but kept for generality).
    if (gtid < rem) {
        int   i   = tail_base + gtid;
        int   lab = __ldg(&l[i]);
        float xv  = __ldg(&x[i]);
        int   c   = i % 23;
        bool  pos = (lab > 0);
        float arg = pos ? xv : (1.0f - xv);
        const float* tab = pos ? s_w1 : s_w0;
        acc = fmaf(tab[c], -__log2f(arg), acc);
    }

    // Intra-block reduce (f32).
    #pragma unroll
    for (int o = 16; o > 0; o >>= 1)
        acc += __shfl_down_sync(0xffffffffu, acc, o);

    const int lane = t & 31, wid = t >> 5;
    if (lane == 0) s_part[wid] = acc;
    __syncthreads();

    if (t == 0) {
        float b = 0.0f;
        #pragma unroll
        for (int w = 0; w < NTHREADS / 32; ++w) b += s_part[w];
        g_part[blockIdx.x] = b;
        __threadfence();
        unsigned ticket = atomicInc(&g_count, NBLOCKS - 1); // wraps to 0
        s_is_last = (ticket == NBLOCKS - 1);
    }
    __syncthreads();

    // Last block: deterministic final reduction in double.
    if (s_is_last) {
        __threadfence();
        double dsum = 0.0;
        for (int i = t; i < NBLOCKS; i += NTHREADS)
            dsum += (double)g_part[i];
        #pragma unroll
        for (int o = 16; o > 0; o >>= 1)
            dsum += __shfl_down_sync(0xffffffffu, dsum, o);
        if (lane == 0) s_dpart[wid] = dsum;
        __syncthreads();
        if (t == 0) {
            double tot = 0.0;
            #pragma unroll
            for (int w = 0; w < NTHREADS / 32; ++w) tot += s_dpart[w];
            out[0] = (float)(tot * (double)inv_n);
        }
    }
}

extern "C" void kernel_launch(void* const* d_in, const int* in_sizes, int n_in,
                              void* d_out, int out_size) {
    const float* x = (const float*)d_in[0];
    const int*   l = (const int*)d_in[1];
    float* out = (float*)d_out;

    long long n = (long long)in_sizes[0];   // total elements (B*C) = 23e6
    int n_u8 = (int)(n >> 3);               // 8-element units
    int rem = (int)(n & 7);
    int tail_base = n_u8 << 3;

    bce_fused_kernel<<<NBLOCKS, NTHREADS>>>(
        x, l, n_u8, rem, tail_base, out, 1.0f / (float)n);
}

// round 12
// speedup vs baseline: 1.0313x; 1.0313x over previous
#include <cuda_runtime.h>
#include <cuda_bf16.h>

// Per-channel class frequencies (compile-time constants from the reference).
__constant__ float c_W[23] = {
    0.0012597430655963838f, 0.0004919313290455535f, 0.0021106513104319356f,
    0.0007678117365508301f, 0.004719881670572202f,  0.000372272357115554f,
    0.029090425620315438f,  0.010056339432617042f,  0.0034817436971298467f,
    0.0003057951504877765f, 0.003995280118329428f,  8.808229878180519e-05f,
    0.012070598793438699f,  0.016788818533845208f,  0.0017832510677901316f,
    0.0008758371973209686f, 0.0005933090691529143f, 0.0031992155689617922f,
    0.003212511010287348f,  0.0016685778863572154f, 0.0009356666832859684f,
    0.0010985358395240233f, 0.00103372056306194f
};

// 592 = 4 CTAs x 148 SMs, single balanced wave at occupancy 4.
// Occ 4 -> 64 regs/thread: room to front-batch 6 x 256-bit loads (48 regs)
// => 32 warps x 6 x 32 B = 6 KB in flight per SM (vs ~4 KB at occ 8).
#define NBLOCKS 592
#define NTHREADS 256
#define LN2F 0.6931471805599453f

__device__ float    g_part[NBLOCKS];
__device__ unsigned g_count = 0;

// Blackwell 256-bit global load.
__device__ __forceinline__ void ld256(const void* p, uint4& a, uint4& b) {
    asm("ld.global.nc.v8.b32 {%0,%1,%2,%3,%4,%5,%6,%7}, [%8];"
        : "=r"(a.x), "=r"(a.y), "=r"(a.z), "=r"(a.w),
          "=r"(b.x), "=r"(b.y), "=r"(b.z), "=r"(b.w)
        : "l"(p));
}

__device__ __forceinline__ float proc8(uint4 xa, uint4 xb, uint4 la, uint4 lb,
                                       int c, const float* s_w0,
                                       const float* s_w1, float acc) {
    float xs[8] = { __uint_as_float(xa.x), __uint_as_float(xa.y),
                    __uint_as_float(xa.z), __uint_as_float(xa.w),
                    __uint_as_float(xb.x), __uint_as_float(xb.y),
                    __uint_as_float(xb.z), __uint_as_float(xb.w) };
    int   ls[8] = { (int)la.x, (int)la.y, (int)la.z, (int)la.w,
                    (int)lb.x, (int)lb.y, (int)lb.z, (int)lb.w };
    #pragma unroll
    for (int j = 0; j < 8; ++j) {
        bool  pos = (ls[j] > 0);
        float arg = pos ? xs[j] : (1.0f - xs[j]);
        const float* tab = pos ? s_w1 : s_w0;
        acc = fmaf(tab[c], -__log2f(arg), acc);
        c = (c == 22) ? 0 : (c + 1);
    }
    return acc;
}

__global__ __launch_bounds__(NTHREADS, 4)
void bce_fused_kernel(const float* __restrict__ x,
                      const int*   __restrict__ l,
                      int n_u8, int rem, int tail_base,
                      float* __restrict__ out, float inv_n) {
    __shared__ float  s_w0[23];   // ln2*(W+1)   : weight when label==0
    __shared__ float  s_w1[23];   // ln2*(1+1/W) : weight when label==1
    __shared__ float  s_part[NTHREADS / 32];
    __shared__ double s_dpart[NTHREADS / 32];
    __shared__ bool   s_is_last;

    const int t = threadIdx.x;
    if (t < 23) {
        float w = c_W[t];
        s_w0[t] = LN2F * (w + 1.0f);
        s_w1[t] = LN2F * (1.0f + __frcp_rn(w));
    }
    __syncthreads();

    const int stride = NBLOCKS * NTHREADS;        // 151552
    const int gtid   = blockIdx.x * NTHREADS + t;

    // Channel advance per stride step in 8-element units: d = (8*stride) % 23.
    const int d  = (int)((8ll * (long long)stride) % 23);
    int c_base   = (int)((8ll * (long long)gtid) % 23);
    int d2 = d + d;  if (d2 >= 23) d2 -= 23;        // 2 steps
    int d3 = d2 + d; if (d3 >= 23) d3 -= 23;        // 3 steps (per iteration)

    float acc = 0.0f;

    int v = gtid;
    // Main loop: 3 grid-stride units, 6 front-batched 256-bit loads.
    for (; v + 2 * stride < n_u8; v += 3 * stride) {
        uint4 xa0, xb0, la0, lb0, xa1, xb1, la1, lb1, xa2, xb2, la2, lb2;
        ld256(x + 8ll * v,                xa0, xb0);
        ld256(l + 8ll * v,                la0, lb0);
        ld256(x + 8ll * (v + stride),     xa1, xb1);
        ld256(l + 8ll * (v + stride),     la1, lb1);
        ld256(x + 8ll * (v + 2 * stride), xa2, xb2);
        ld256(l + 8ll * (v + 2 * stride), la2, lb2);

        int c0 = c_base;
        int c1 = c0 + d;  if (c1 >= 23) c1 -= 23;
        int c2 = c0 + d2; if (c2 >= 23) c2 -= 23;
        c_base += d3; if (c_base >= 23) c_base -= 23;

        acc = proc8(xa0, xb0, la0, lb0, c0, s_w0, s_w1, acc);
        acc = proc8(xa1, xb1, la1, lb1, c1, s_w0, s_w1, acc);
        acc = proc8(xa2, xb2, la2, lb2, c2, s_w0, s_w1, acc);
    }
    // Remainder: 0-2 units.
    for (; v < n_u8; v += stride) {
        uint4 xa, xb, la, lb;
        ld256(x + 8ll * v, xa, xb);
        ld256(l + 8ll * v, la, lb);
        acc = proc8(xa, xb, la, lb, c_base, s_w0, s_w1, acc);
        c_base += d; if (c_base >= 23) c_base -= 23;
    }

    // Scalar tail (n % 8 elements; 0 for B*C = 23e6 but kept for generality).
    if (gtid < rem) {
        int   i   = tail_base + gtid;
        int   lab = __ldg(&l[i]);
        float xv  = __ldg(&x[i]);
        int   c   = i % 23;
        bool  pos = (lab > 0);
        float arg = pos ? xv : (1.0f - xv);
        const float* tab = pos ? s_w1 : s_w0;
        acc = fmaf(tab[c], -__log2f(arg), acc);
    }

    // Intra-block reduce (f32).
    #pragma unroll
    for (int o = 16; o > 0; o >>= 1)
        acc += __shfl_down_sync(0xffffffffu, acc, o);

    const int lane = t & 31, wid = t >> 5;
    if (lane == 0) s_part[wid] = acc;
    __syncthreads();

    if (t == 0) {
        float b = 0.0f;
        #pragma unroll
        for (int w = 0; w < NTHREADS / 32; ++w) b += s_part[w];
        g_part[blockIdx.x] = b;
        __threadfence();
        unsigned ticket = atomicInc(&g_count, NBLOCKS - 1); // wraps to 0
        s_is_last = (ticket == NBLOCKS - 1);
    }
    __syncthreads();

    // Last block: deterministic final reduction in double.
    if (s_is_last) {
        __threadfence();
        double dsum = 0.0;
        for (int i = t; i < NBLOCKS; i += NTHREADS)
            dsum += (double)g_part[i];
        #pragma unroll
        for (int o = 16; o > 0; o >>= 1)
            dsum += __shfl_down_sync(0xffffffffu, dsum, o);
        if (lane == 0) s_dpart[wid] = dsum;
        __syncthreads();
        if (t == 0) {
            double tot = 0.0;
            #pragma unroll
            for (int w = 0; w < NTHREADS / 32; ++w) tot += s_dpart[w];
            out[0] = (float)(tot * (double)inv_n);
        }
    }
}

extern "C" void kernel_launch(void* const* d_in, const int* in_sizes, int n_in,
                              void* d_out, int out_size) {
    const float* x = (const float*)d_in[0];
    const int*   l = (const int*)d_in[1];
    float* out = (float*)d_out;

    long long n = (long long)in_sizes[0];   // total elements (B*C) = 23e6
    int n_u8 = (int)(n >> 3);               // 8-element units
    int rem = (int)(n & 7);
    int tail_base = n_u8 << 3;

    bce_fused_kernel<<<NBLOCKS, NTHREADS>>>(
        x, l, n_u8, rem, tail_base, out, 1.0f / (float)n);
}

// round 13
// speedup vs baseline: 1.1012x; 1.0678x over previous
#include <cuda_runtime.h>
#include <cuda_bf16.h>

// Per-channel class frequencies (compile-time constants from the reference).
__constant__ float c_W[23] = {
    0.0012597430655963838f, 0.0004919313290455535f, 0.0021106513104319356f,
    0.0007678117365508301f, 0.004719881670572202f,  0.000372272357115554f,
    0.029090425620315438f,  0.010056339432617042f,  0.0034817436971298467f,
    0.0003057951504877765f, 0.003995280118329428f,  8.808229878180519e-05f,
    0.012070598793438699f,  0.016788818533845208f,  0.0017832510677901316f,
    0.0008758371973209686f, 0.0005933090691529143f, 0.0031992155689617922f,
    0.003212511010287348f,  0.0016685778863572154f, 0.0009356666832859684f,
    0.0010985358395240233f, 0.00103372056306194f
};

// 1184 = 8 CTAs x 148 SMs: balanced single wave (empirical optimum, R2/R8).
#define NBLOCKS 1184
#define NTHREADS 256
#define LN2F 0.6931471805599453f

// Scratch (no allocations allowed). g_acc is reset to 0 by the last-ticket
// block every run, and g_count self-wraps via atomicInc -> graph-replay safe.
__device__ double   g_acc   = 0.0;
__device__ unsigned g_count = 0;

__global__ __launch_bounds__(NTHREADS, 8)
void bce_fused_kernel(const float4* __restrict__ x4,
                      const int4*   __restrict__ l4,
                      int n_vec, int rem,
                      const float* __restrict__ x_tail,
                      const int*   __restrict__ l_tail,
                      int tail_base,
                      float* __restrict__ out, float inv_n) {
    __shared__ float s_w0[23];   // ln2*(W+1)   : weight when label==0
    __shared__ float s_w1[23];   // ln2*(1+1/W) : weight when label==1
    __shared__ float s_part[NTHREADS / 32];

    const int t = threadIdx.x;
    if (t < 23) {
        float w = c_W[t];
        s_w0[t] = LN2F * (w + 1.0f);
        s_w1[t] = LN2F * (1.0f + __frcp_rn(w));
    }
    __syncthreads();

    const int stride = NBLOCKS * NTHREADS;
    const int gtid   = blockIdx.x * NTHREADS + t;

    // Channel of the first element of this thread's first vector, and the
    // per-iteration advance (4*stride mod 23).
    int c_base = (int)((4ll * (long long)gtid) % 23);
    const int d = (int)((4ll * (long long)stride) % 23);

    float acc = 0.0f;

    // Plain grid-stride loop, compiler-chosen unroll (empirical optimum).
    for (int v = gtid; v < n_vec; v += stride) {
        float4 xv = __ldg(&x4[v]);
        int4   lv = __ldg(&l4[v]);

        int c = c_base;
        c_base += d; if (c_base >= 23) c_base -= 23;

        float xs[4] = { xv.x, xv.y, xv.z, xv.w };
        int   ls[4] = { lv.x, lv.y, lv.z, lv.w };
        #pragma unroll
        for (int j = 0; j < 4; ++j) {
            bool  pos = (ls[j] > 0);
            float arg = pos ? xs[j] : (1.0f - xs[j]);
            const float* tab = pos ? s_w1 : s_w0;   // one LDS per element
            acc = fmaf(tab[c], -__log2f(arg), acc);
            c = (c == 22) ? 0 : (c + 1);
        }
    }

    // Scalar tail (n % 4 elements; 0 for B*C = 23e6 but kept for generality).
    if (gtid < rem) {
        int   i   = tail_base + gtid;
        int   lab = __ldg(&l_tail[gtid]);
        float xv  = __ldg(&x_tail[gtid]);
        int   c   = i % 23;
        bool  pos = (lab > 0);
        float arg = pos ? xv : (1.0f - xv);
        const float* tab = pos ? s_w1 : s_w0;
        acc = fmaf(tab[c], -__log2f(arg), acc);
    }

    // Intra-block reduce (f32).
    #pragma unroll
    for (int o = 16; o > 0; o >>= 1)
        acc += __shfl_down_sync(0xffffffffu, acc, o);

    const int lane = t & 31, wid = t >> 5;
    if (lane == 0) s_part[wid] = acc;
    __syncthreads();

    if (t == 0) {
        float b = 0.0f;
        #pragma unroll
        for (int w = 0; w < NTHREADS / 32; ++w) b += s_part[w];
        // Accumulate in double directly (overlaps with other blocks' compute;
        // avoids a serialized 1184-element reduction after the grid drains).
        atomicAdd(&g_acc, (double)b);
        __threadfence();
        unsigned ticket = atomicInc(&g_count, NBLOCKS - 1); // wraps to 0
        if (ticket == NBLOCKS - 1) {
            // All blocks' atomicAdds precede their atomicInc; we're last.
            double tot = g_acc;
            out[0] = (float)(tot * (double)inv_n);
            g_acc = 0.0;            // reset for next graph replay
            __threadfence();
        }
    }
}

extern "C" void kernel_launch(void* const* d_in, const int* in_sizes, int n_in,
                              void* d_out, int out_size) {
    const float* x = (const float*)d_in[0];
    const int*   l = (const int*)d_in[1];
    float* out = (float*)d_out;

    long long n = (long long)in_sizes[0];   // total elements (B*C) = 23e6
    int n_vec = (int)(n >> 2);
    int rem = (int)(n & 3);
    int tail_base = n_vec << 2;

    bce_fused_kernel<<<NBLOCKS, NTHREADS>>>(
        (const float4*)x, (const int4*)l, n_vec, rem,
        x + (long long)tail_base, l + (long long)tail_base, tail_base,
        out, 1.0f / (float)n);
}